// round 5
// baseline (speedup 1.0000x reference)
#include <cuda_runtime.h>

typedef unsigned long long ull;

#define TN      64
#define THREADS 256
#define CC      128
#define KD      32

// float offsets in dynamic smem
#define XSN_F   0                      // xsn [64 n][136] node-major, lives whole kernel
#define XSN_NF  (TN * 136)             // 8704 floats
#define REG_F   XSN_NF                 // region: W1 [128][128] (16384 f) -> hs[64][136] + W2s[128][32]
#define HS_F    REG_F
#define W2_F    (REG_F + TN * 136)
#define SS_F    (REG_F + CC * CC)      // ss [64][32]
#define IB_I    (SS_F + TN * KD)
#define SMEM_FLOATS (IB_I + TN)
#define SMEM_BYTES  (SMEM_FLOATS * 4)  // 108800

static __device__ __forceinline__ ull pk2(float lo, float hi) {
    ull r; asm("mov.b64 %0,{%1,%2};" : "=l"(r) : "f"(lo), "f"(hi)); return r;
}
static __device__ __forceinline__ float2 upk2(ull v) {
    float2 f; asm("mov.b64 {%0,%1},%2;" : "=f"(f.x), "=f"(f.y) : "l"(v)); return f;
}
static __device__ __forceinline__ ull ffma2_(ull a, ull b, ull c) {
    ull d; asm("fma.rn.f32x2 %0,%1,%2,%3;" : "=l"(d) : "l"(a), "l"(b), "l"(c)); return d;
}

__global__ void hp_zero_kernel(float4* __restrict__ o, int n4) {
    int i = blockIdx.x * blockDim.x + threadIdx.x;
    float4 z = make_float4(0.f, 0.f, 0.f, 0.f);
    for (; i < n4; i += gridDim.x * blockDim.x) o[i] = z;
}

__global__ __launch_bounds__(THREADS, 2)
void hp_main_kernel(const float* __restrict__ x, const int* __restrict__ batch,
                    const float* __restrict__ W1, const float* __restrict__ b1,
                    const float* __restrict__ W2, const float* __restrict__ b2,
                    float* __restrict__ out, float* __restrict__ s_out, int N)
{
    extern __shared__ __align__(16) float smem[];
    float4* xsn4 = (float4*)(smem + XSN_F);      // pitch 34 f4
    float4* w1s4 = (float4*)(smem + REG_F);      // pitch 32 f4
    float*  hs   = smem + HS_F;                  // pitch 136 f
    float4* hs4  = (float4*)hs;                  // pitch 34 f4
    float4* w2s4 = (float4*)(smem + W2_F);       // pitch 8 f4
    float*  ss   = smem + SS_F;                  // pitch 32 f
    float4* ss4  = (float4*)ss;                  // pitch 8 f4
    int*    ib   = (int*)(smem + IB_I);

    const int tid  = threadIdx.x;
    const int lane = tid & 31;
    const int wrp  = tid >> 5;          // 0..7
    const int n0   = blockIdx.x * TN;
    const int nvalid = min(TN, N - n0);

    // ================= staging: ib, xsn (node-major, coalesced), W1 =================
    if (tid < TN) ib[tid] = (n0 + tid < N) ? batch[n0 + tid] : -1;

    {
        const float4* xg = (const float4*)x;
        #pragma unroll
        for (int it = 0; it < (TN * 32) / THREADS; ++it) {   // 8 iters
            int idx = it * THREADS + tid;
            int n = idx >> 5, g = idx & 31;
            float4 v = make_float4(0.f, 0.f, 0.f, 0.f);
            if (n < nvalid) v = xg[(size_t)(n0 + n) * 32 + g];
            xsn4[n * 34 + g] = v;
        }
        const float4* wg = (const float4*)W1;
        #pragma unroll
        for (int it = 0; it < (CC * 32) / THREADS; ++it)     // 16 iters
            w1s4[it * THREADS + tid] = wg[it * THREADS + tid];
    }
    __syncthreads();

    // ===== stage 1: H = relu(X @ W1 + b1) =====
    // tc = tid&15 -> cols {4tc..4tc+3} U {64+4tc..+3}; ty = tid>>4 (0..15) -> nodes n = ty + 16r
    {
        const int tc = tid & 15;
        const int ty = tid >> 4;
        float4 b1a = ((const float4*)b1)[tc];
        float4 b1b = ((const float4*)b1)[16 + tc];
        ull acc[4][4];
        #pragma unroll
        for (int r = 0; r < 4; ++r) {
            acc[r][0] = pk2(b1a.x, b1a.y);
            acc[r][1] = pk2(b1a.z, b1a.w);
            acc[r][2] = pk2(b1b.x, b1b.y);
            acc[r][3] = pk2(b1b.z, b1b.w);
        }

        for (int k4 = 0; k4 < 32; ++k4) {
            float4 xf[4];
            #pragma unroll
            for (int r = 0; r < 4; ++r) xf[r] = xsn4[(ty + 16 * r) * 34 + k4];
            #pragma unroll
            for (int kk = 0; kk < 4; ++kk) {
                float4 wA = w1s4[(k4 * 4 + kk) * 32 + tc];
                float4 wB = w1s4[(k4 * 4 + kk) * 32 + 16 + tc];
                ull wp0 = pk2(wA.x, wA.y), wp1 = pk2(wA.z, wA.w);
                ull wp2 = pk2(wB.x, wB.y), wp3 = pk2(wB.z, wB.w);
                #pragma unroll
                for (int r = 0; r < 4; ++r) {
                    float xk = (kk == 0) ? xf[r].x : (kk == 1) ? xf[r].y
                             : (kk == 2) ? xf[r].z : xf[r].w;
                    ull xp = pk2(xk, xk);
                    acc[r][0] = ffma2_(xp, wp0, acc[r][0]);
                    acc[r][1] = ffma2_(xp, wp1, acc[r][1]);
                    acc[r][2] = ffma2_(xp, wp2, acc[r][2]);
                    acc[r][3] = ffma2_(xp, wp3, acc[r][3]);
                }
            }
        }
        __syncthreads();   // all warps done reading W1 before hs/W2 overlay it

        #pragma unroll
        for (int r = 0; r < 4; ++r) {
            int n = ty + 16 * r;
            float2 a0 = upk2(acc[r][0]), a1 = upk2(acc[r][1]);
            float2 a2 = upk2(acc[r][2]), a3 = upk2(acc[r][3]);
            *(float4*)&hs[n * 136 + tc * 4] =
                make_float4(fmaxf(a0.x, 0.f), fmaxf(a0.y, 0.f),
                            fmaxf(a1.x, 0.f), fmaxf(a1.y, 0.f));
            *(float4*)&hs[n * 136 + 64 + tc * 4] =
                make_float4(fmaxf(a2.x, 0.f), fmaxf(a2.y, 0.f),
                            fmaxf(a3.x, 0.f), fmaxf(a3.y, 0.f));
        }
    }
    {
        const float4* w2g = (const float4*)W2;
        #pragma unroll
        for (int it = 0; it < (CC * 8) / THREADS; ++it)      // 4 iters
            w2s4[it * THREADS + tid] = w2g[it * THREADS + tid];
    }
    __syncthreads();

    // ===== stage 2: logits = H @ W2 + b2 =====
    // kg = tid&7 -> k = 4kg..4kg+3 ; nq = tid>>3 (0..31) -> nodes nq, nq+32
    {
        const int kg = tid & 7;
        const int nq = tid >> 3;
        float4 b2v = ((const float4*)b2)[kg];
        ull acc[2][2];
        #pragma unroll
        for (int a = 0; a < 2; ++a) {
            acc[a][0] = pk2(b2v.x, b2v.y);
            acc[a][1] = pk2(b2v.z, b2v.w);
        }
        for (int j4 = 0; j4 < 32; ++j4) {
            float4 h0 = hs4[nq * 34 + j4];
            float4 h1 = hs4[(nq + 32) * 34 + j4];
            #pragma unroll
            for (int jj = 0; jj < 4; ++jj) {
                float4 w = w2s4[(j4 * 4 + jj) * 8 + kg];
                ull wp0 = pk2(w.x, w.y), wp1 = pk2(w.z, w.w);
                float hv0 = (jj == 0) ? h0.x : (jj == 1) ? h0.y : (jj == 2) ? h0.z : h0.w;
                float hv1 = (jj == 0) ? h1.x : (jj == 1) ? h1.y : (jj == 2) ? h1.z : h1.w;
                ull hp0 = pk2(hv0, hv0);
                ull hp1 = pk2(hv1, hv1);
                acc[0][0] = ffma2_(hp0, wp0, acc[0][0]);
                acc[0][1] = ffma2_(hp0, wp1, acc[0][1]);
                acc[1][0] = ffma2_(hp1, wp0, acc[1][0]);
                acc[1][1] = ffma2_(hp1, wp1, acc[1][1]);
            }
        }
        #pragma unroll
        for (int a = 0; a < 2; ++a) {
            int n = nq + 32 * a;
            float2 p0 = upk2(acc[a][0]), p1 = upk2(acc[a][1]);
            ss4[n * 8 + kg] = make_float4(p0.x, p0.y, p1.x, p1.y);
        }
    }
    __syncthreads();

    // ===== stage 3: softmax per node (8 warps x 8 nodes, lane = k) =====
    {
        #pragma unroll
        for (int i = 0; i < 8; ++i) {
            int n = wrp * 8 + i;
            float v = ss[n * KD + lane];
            float m = v;
            #pragma unroll
            for (int o = 16; o > 0; o >>= 1) m = fmaxf(m, __shfl_xor_sync(0xffffffffu, m, o));
            float e = __expf(v - m);
            float sum = e;
            #pragma unroll
            for (int o = 16; o > 0; o >>= 1) sum += __shfl_xor_sync(0xffffffffu, sum, o);
            float sv = e / sum;
            ss[n * KD + lane] = sv;
            if (n0 + n < N) s_out[(size_t)(n0 + n) * KD + lane] = sv;
        }
    }
    __syncthreads();

    // ===== stage 4: out[b][k][c] += sum_n s[n][k] * x[n][c] =====
    // warp: kh = (wrp>>2)*16 (k half), cq = (wrp&3)*32 (c chunk)
    // lane: cl=lane&7 -> c = cq+cl*4 ; kq=lane>>3 -> k = kh+kq*4 .. +3
    {
        const int cl = lane & 7;
        const int kq = lane >> 3;
        const int kh = (wrp >> 2) * 16;
        const int cq = (wrp & 3) * 32;
        const int c0 = cq + cl * 4;
        const int k0 = kh + kq * 4;

        int bmin = ib[0];
        int bmax = ib[nvalid - 1];
        for (int b = bmin; b <= bmax; ++b) {
            ull acc[4][2];
            #pragma unroll
            for (int kk = 0; kk < 4; ++kk) { acc[kk][0] = 0ull; acc[kk][1] = 0ull; }

            for (int n = 0; n < TN; ++n) {
                if (ib[n] != b) continue;   // uniform across block
                float4 sA = ss4[n * 8 + (kh >> 2) + kq];     // s[k0..k0+3]
                float4 xv = xsn4[n * 34 + (cq >> 2) + cl];   // x[c0..c0+3]
                ull xp0 = pk2(xv.x, xv.y);
                ull xp1 = pk2(xv.z, xv.w);
                float sk[4] = {sA.x, sA.y, sA.z, sA.w};
                #pragma unroll
                for (int kk = 0; kk < 4; ++kk) {
                    ull sp = pk2(sk[kk], sk[kk]);
                    acc[kk][0] = ffma2_(sp, xp0, acc[kk][0]);
                    acc[kk][1] = ffma2_(sp, xp1, acc[kk][1]);
                }
            }
            float* ob = out + (size_t)b * (KD * CC);
            #pragma unroll
            for (int kk = 0; kk < 4; ++kk) {
                float2 f0 = upk2(acc[kk][0]);
                float2 f1 = upk2(acc[kk][1]);
                float* p = &ob[(k0 + kk) * CC + c0];
                atomicAdd(p + 0, f0.x);
                atomicAdd(p + 1, f0.y);
                atomicAdd(p + 2, f1.x);
                atomicAdd(p + 3, f1.y);
            }
        }
    }
}

extern "C" void kernel_launch(void* const* d_in, const int* in_sizes, int n_in,
                              void* d_out, int out_size)
{
    const float* x     = (const float*)d_in[0];
    const int*   batch = (const int*)d_in[1];
    const float* W1    = (const float*)d_in[2];
    const float* b1    = (const float*)d_in[3];
    const float* W2    = (const float*)d_in[4];
    const float* b2    = (const float*)d_in[5];

    const int N = in_sizes[1];
    float* out = (float*)d_out;
    size_t out_elems = (size_t)out_size - (size_t)N * KD;   // B*K*C
    float* s_out = out + out_elems;

    // zero the pooled-output region (poisoned by harness)
    {
        int n4 = (int)(out_elems / 4);
        int blocks = (n4 + 255) / 256;
        if (blocks > 512) blocks = 512;
        hp_zero_kernel<<<blocks, 256>>>((float4*)out, n4);
    }

    cudaFuncSetAttribute(hp_main_kernel,
                         cudaFuncAttributeMaxDynamicSharedMemorySize, SMEM_BYTES);
    int nb = (N + TN - 1) / TN;
    hp_main_kernel<<<nb, THREADS, SMEM_BYTES>>>(x, batch, W1, b1, W2, b2, out, s_out, N);
}

// round 7
// speedup vs baseline: 1.0054x; 1.0054x over previous
#include <cuda_runtime.h>
#include <cstdint>

typedef unsigned long long ull;

#define TN      128
#define THREADS 256
#define CC      128
#define KD      32

// float offsets in dynamic smem
#define XN_F   0                        // x node-major [128][132]
#define W1_F   16896                    // W1 natural [k][c] pitch 136 ; H overlays (pitch 132)
#define HS_F   W1_F
#define W2_F   34304                    // W2 natural [j][k] pitch 40
#define SS_F   39424                    // logits/s [128][36]
#define B1_F   44032
#define B2_F   44160
#define IB_I   44192
#define SMEM_FLOATS 44320
#define SMEM_BYTES  (SMEM_FLOATS * 4)   // 177280

// ---------- helpers ----------
static __device__ __forceinline__ ull pk2(float lo, float hi) {
    ull r; asm("mov.b64 %0,{%1,%2};" : "=l"(r) : "f"(lo), "f"(hi)); return r;
}
static __device__ __forceinline__ float2 upk2(ull v) {
    float2 f; asm("mov.b64 {%0,%1},%2;" : "=f"(f.x), "=f"(f.y) : "l"(v)); return f;
}
static __device__ __forceinline__ ull ffma2_(ull a, ull b, ull c) {
    ull d; asm("fma.rn.f32x2 %0,%1,%2,%3;" : "=l"(d) : "l"(a), "l"(b), "l"(c)); return d;
}
static __device__ __forceinline__ uint32_t cvt_tf32(float f) {
    uint32_t r; asm("cvt.rna.tf32.f32 %0, %1;" : "=r"(r) : "f"(f)); return r;
}
static __device__ __forceinline__ void split_tf32(float f, uint32_t& h, uint32_t& l) {
    h = cvt_tf32(f);
    l = cvt_tf32(f - __uint_as_float(h));
}
static __device__ __forceinline__ void mma_tf32(float* d, const uint32_t* a,
                                                uint32_t b0, uint32_t b1) {
    asm volatile(
        "mma.sync.aligned.m16n8k8.row.col.f32.tf32.tf32.f32 "
        "{%0,%1,%2,%3}, {%4,%5,%6,%7}, {%8,%9}, {%0,%1,%2,%3};"
        : "+f"(d[0]), "+f"(d[1]), "+f"(d[2]), "+f"(d[3])
        : "r"(a[0]), "r"(a[1]), "r"(a[2]), "r"(a[3]), "r"(b0), "r"(b1));
}

__global__ void hp_zero_kernel(float4* __restrict__ o, int n4) {
    int i = blockIdx.x * blockDim.x + threadIdx.x;
    float4 z = make_float4(0.f, 0.f, 0.f, 0.f);
    for (; i < n4; i += gridDim.x * blockDim.x) o[i] = z;
}

__global__ __launch_bounds__(THREADS, 1)
void hp_main_kernel(const float* __restrict__ x, const int* __restrict__ batch,
                    const float* __restrict__ W1, const float* __restrict__ b1,
                    const float* __restrict__ W2, const float* __restrict__ b2,
                    float* __restrict__ out, float* __restrict__ s_out, int N)
{
    extern __shared__ __align__(16) float smem[];
    float*  xn   = smem + XN_F;          // pitch 132
    float4* xn4  = (float4*)xn;          // pitch 33
    float*  w1s  = smem + W1_F;          // pitch 136
    float4* w1s4 = (float4*)w1s;         // pitch 34
    float*  Hs   = smem + HS_F;          // pitch 132 (overlays W1)
    float*  w2s  = smem + W2_F;          // pitch 40
    float4* w2s4 = (float4*)w2s;         // pitch 10
    float*  ss   = smem + SS_F;          // pitch 36
    float4* ss4  = (float4*)ss;          // pitch 9
    float*  b1s  = smem + B1_F;
    float*  b2s  = smem + B2_F;
    int*    ib   = (int*)(smem + IB_I);

    const int tid  = threadIdx.x;
    const int lane = tid & 31;
    const int wid  = tid >> 5;          // 0..7
    const int qr   = lane >> 2;         // 0..7
    const int qc   = lane & 3;          // 0..3
    const int n0   = blockIdx.x * TN;
    const int nvalid = min(TN, N - n0);

    // ================= staging =================
    if (tid < TN) ib[tid] = (n0 + tid < N) ? batch[n0 + tid] : -1;
    if (tid < CC) b1s[tid] = b1[tid];
    if (tid < KD) b2s[tid] = b2[tid];
    {
        const float4* xg = (const float4*)x;
        #pragma unroll
        for (int it = 0; it < (TN * 32) / THREADS; ++it) {   // 16
            int idx = it * THREADS + tid;
            int n = idx >> 5, g = idx & 31;
            float4 v = make_float4(0.f, 0.f, 0.f, 0.f);
            if (n < nvalid) v = xg[(size_t)(n0 + n) * 32 + g];
            xn4[n * 33 + g] = v;
        }
        const float4* wg = (const float4*)W1;
        #pragma unroll
        for (int it = 0; it < (CC * 32) / THREADS; ++it) {   // 16
            int idx = it * THREADS + tid;
            int k = idx >> 5, c4 = idx & 31;
            w1s4[k * 34 + c4] = wg[idx];
        }
        const float4* w2g = (const float4*)W2;
        #pragma unroll
        for (int it = 0; it < (CC * 8) / THREADS; ++it) {    // 4
            int idx = it * THREADS + tid;
            int j = idx >> 3, k4 = idx & 7;
            w2s4[j * 10 + k4] = w2g[idx];
        }
    }
    __syncthreads();

    // ===== GEMM1: H = relu(X @ W1 + b1)  via 3xTF32 mma.sync =====
    // warp: mh = wid>>2 (node half), nw = wid&3 (c quarter). 4 m-tiles x 4 n-tiles.
    float acc[4][4][4];
    {
        #pragma unroll
        for (int mt = 0; mt < 4; ++mt)
            #pragma unroll
            for (int nt = 0; nt < 4; ++nt)
                #pragma unroll
                for (int e = 0; e < 4; ++e) acc[mt][nt][e] = 0.f;

        const int mbase = (wid >> 2) * 64;
        const int cbase = (wid & 3) * 32;

        for (int ks = 0; ks < 16; ++ks) {
            const int kb = ks * 8;
            uint32_t ah[4][4], al[4][4];
            #pragma unroll
            for (int mt = 0; mt < 4; ++mt) {
                int r0 = mbase + mt * 16 + qr;
                float f0 = xn[r0 * 132 + kb + qc];
                float f1 = xn[(r0 + 8) * 132 + kb + qc];
                float f2 = xn[r0 * 132 + kb + qc + 4];
                float f3 = xn[(r0 + 8) * 132 + kb + qc + 4];
                split_tf32(f0, ah[mt][0], al[mt][0]);
                split_tf32(f1, ah[mt][1], al[mt][1]);
                split_tf32(f2, ah[mt][2], al[mt][2]);
                split_tf32(f3, ah[mt][3], al[mt][3]);
            }
            #pragma unroll
            for (int nt = 0; nt < 4; ++nt) {
                int cb = cbase + nt * 8 + qr;
                float g0 = w1s[(kb + qc) * 136 + cb];
                float g1 = w1s[(kb + qc + 4) * 136 + cb];
                uint32_t bh0, bl0, bh1, bl1;
                split_tf32(g0, bh0, bl0);
                split_tf32(g1, bh1, bl1);
                #pragma unroll
                for (int mt = 0; mt < 4; ++mt) {
                    mma_tf32(acc[mt][nt], ah[mt], bh0, bh1);
                    mma_tf32(acc[mt][nt], al[mt], bh0, bh1);
                    uint32_t abl[4] = {ah[mt][0], ah[mt][1], ah[mt][2], ah[mt][3]};
                    mma_tf32(acc[mt][nt], abl, bl0, bl1);
                }
            }
        }
    }
    __syncthreads();   // all warps done reading W1 before H overlays it

    // ---- epilogue 1: relu + bias, write H node-major (pitch 132) ----
    {
        const int mbase = (wid >> 2) * 64;
        const int cbase = (wid & 3) * 32;
        #pragma unroll
        for (int mt = 0; mt < 4; ++mt) {
            int r0 = mbase + mt * 16 + qr;
            #pragma unroll
            for (int nt = 0; nt < 4; ++nt) {
                int cb = cbase + nt * 8 + qc * 2;
                float2 v0, v1;
                v0.x = fmaxf(acc[mt][nt][0] + b1s[cb],     0.f);
                v0.y = fmaxf(acc[mt][nt][1] + b1s[cb + 1], 0.f);
                v1.x = fmaxf(acc[mt][nt][2] + b1s[cb],     0.f);
                v1.y = fmaxf(acc[mt][nt][3] + b1s[cb + 1], 0.f);
                *(float2*)&Hs[r0 * 132 + cb]       = v0;
                *(float2*)&Hs[(r0 + 8) * 132 + cb] = v1;
            }
        }
    }
    __syncthreads();

    // ===== GEMM2: logits = H @ W2 + b2  (warp = 16-node m-tile, 4 n-tiles of 8 k) =====
    {
        float a2[4][4];
        #pragma unroll
        for (int nt = 0; nt < 4; ++nt)
            #pragma unroll
            for (int e = 0; e < 4; ++e) a2[nt][e] = 0.f;

        const int r0 = wid * 16 + qr;
        for (int js = 0; js < 16; ++js) {
            const int jb = js * 8;
            uint32_t ah[4], al[4];
            {
                float f0 = Hs[r0 * 132 + jb + qc];
                float f1 = Hs[(r0 + 8) * 132 + jb + qc];
                float f2 = Hs[r0 * 132 + jb + qc + 4];
                float f3 = Hs[(r0 + 8) * 132 + jb + qc + 4];
                split_tf32(f0, ah[0], al[0]);
                split_tf32(f1, ah[1], al[1]);
                split_tf32(f2, ah[2], al[2]);
                split_tf32(f3, ah[3], al[3]);
            }
            #pragma unroll
            for (int nt = 0; nt < 4; ++nt) {
                int kb = nt * 8 + qr;
                float g0 = w2s[(jb + qc) * 40 + kb];
                float g1 = w2s[(jb + qc + 4) * 40 + kb];
                uint32_t bh0, bl0, bh1, bl1;
                split_tf32(g0, bh0, bl0);
                split_tf32(g1, bh1, bl1);
                mma_tf32(a2[nt], ah, bh0, bh1);
                mma_tf32(a2[nt], al, bh0, bh1);
                mma_tf32(a2[nt], ah, bl0, bl1);
            }
        }
        #pragma unroll
        for (int nt = 0; nt < 4; ++nt) {
            int kb = nt * 8 + qc * 2;
            ss[r0 * 36 + kb]           = a2[nt][0] + b2s[kb];
            ss[r0 * 36 + kb + 1]       = a2[nt][1] + b2s[kb + 1];
            ss[(r0 + 8) * 36 + kb]     = a2[nt][2] + b2s[kb];
            ss[(r0 + 8) * 36 + kb + 1] = a2[nt][3] + b2s[kb + 1];
        }
    }
    __syncthreads();

    // ===== softmax per node (8 warps x 16 nodes, lane = k) =====
    {
        #pragma unroll
        for (int i = 0; i < 16; ++i) {
            int n = wid * 16 + i;
            float v = ss[n * 36 + lane];
            float m = v;
            #pragma unroll
            for (int o = 16; o > 0; o >>= 1) m = fmaxf(m, __shfl_xor_sync(0xffffffffu, m, o));
            float e = __expf(v - m);
            float sum = e;
            #pragma unroll
            for (int o = 16; o > 0; o >>= 1) sum += __shfl_xor_sync(0xffffffffu, sum, o);
            float sv = e / sum;
            ss[n * 36 + lane] = sv;
            if (n < nvalid) s_out[(size_t)(n0 + n) * KD + lane] = sv;
        }
    }
    __syncthreads();

    // ===== stage 4: out[b][k][c] += sum_n s[n][k] * x[n][c]  (scalar f32x2) =====
    {
        const int cl = lane & 7;
        const int kq = lane >> 3;
        const int kh = (wid >> 2) * 16;
        const int cq = (wid & 3) * 32;
        const int c0 = cq + cl * 4;
        const int k0 = kh + kq * 4;

        int bmin = ib[0];
        int bmax = ib[nvalid - 1];
        for (int b = bmin; b <= bmax; ++b) {
            ull acc4[4][2];
            #pragma unroll
            for (int kk = 0; kk < 4; ++kk) { acc4[kk][0] = 0ull; acc4[kk][1] = 0ull; }
            for (int n = 0; n < TN; ++n) {
                if (ib[n] != b) continue;        // uniform across block
                float4 sA = ss4[n * 9 + (k0 >> 2)];
                float4 xv = xn4[n * 33 + (c0 >> 2)];
                ull xp0 = pk2(xv.x, xv.y);
                ull xp1 = pk2(xv.z, xv.w);
                float sk[4] = {sA.x, sA.y, sA.z, sA.w};
                #pragma unroll
                for (int kk = 0; kk < 4; ++kk) {
                    ull sp = pk2(sk[kk], sk[kk]);
                    acc4[kk][0] = ffma2_(sp, xp0, acc4[kk][0]);
                    acc4[kk][1] = ffma2_(sp, xp1, acc4[kk][1]);
                }
            }
            float* ob = out + (size_t)b * (KD * CC);
            #pragma unroll
            for (int kk = 0; kk < 4; ++kk) {
                float2 f0 = upk2(acc4[kk][0]);
                float2 f1 = upk2(acc4[kk][1]);
                float* p = &ob[(k0 + kk) * CC + c0];
                atomicAdd(p + 0, f0.x);
                atomicAdd(p + 1, f0.y);
                atomicAdd(p + 2, f1.x);
                atomicAdd(p + 3, f1.y);
            }
        }
    }
}

extern "C" void kernel_launch(void* const* d_in, const int* in_sizes, int n_in,
                              void* d_out, int out_size)
{
    const float* x     = (const float*)d_in[0];
    const int*   batch = (const int*)d_in[1];
    const float* W1    = (const float*)d_in[2];
    const float* b1    = (const float*)d_in[3];
    const float* W2    = (const float*)d_in[4];
    const float* b2    = (const float*)d_in[5];

    const int N = in_sizes[1];
    float* out = (float*)d_out;
    size_t out_elems = (size_t)out_size - (size_t)N * KD;   // B*K*C
    float* s_out = out + out_elems;

    {   // zero pooled output (harness poisons it)
        int n4 = (int)(out_elems / 4);
        int blocks = (n4 + 255) / 256;
        if (blocks > 512) blocks = 512;
        hp_zero_kernel<<<blocks, 256>>>((float4*)out, n4);
    }

    cudaFuncSetAttribute(hp_main_kernel,
                         cudaFuncAttributeMaxDynamicSharedMemorySize, SMEM_BYTES);
    int nb = (N + TN - 1) / TN;
    hp_main_kernel<<<nb, THREADS, SMEM_BYTES>>>(x, batch, W1, b1, W2, b2, out, s_out, N);
}

// round 8
// speedup vs baseline: 1.3647x; 1.3574x over previous
#include <cuda_runtime.h>
#include <cuda_bf16.h>
#include <cstdint>

typedef unsigned long long ull;

#define TN      128
#define THREADS 256
#define CC      128
#define KD      32

// float/uint32 slot offsets in dynamic smem
#define XF_F    0                       // x fp32 [128][132]
#define XH_F    16896                   // X hi bf16-pairs uint32 [128][68]; H hi overlays after GEMM1
#define XL_F    25600                   // X lo ; H lo overlays
#define W1H_F   34304                   // W1^T hi pairs [128c][68]; ss overlays after GEMM1
#define W1L_F   43008
#define W2H_F   51712                   // W2^T hi pairs [32k][68]
#define W2L_F   53888
#define SS_F    34304                   // logits/s fp32 [128][36] (overlays W1H)
#define B1_F    56064
#define B2_F    56192
#define IB_I    56224
#define SMEM_FLOATS 56352
#define SMEM_BYTES  (SMEM_FLOATS * 4)   // 225408

__device__ uint32_t g_W1hl[2 * CC * 68];   // [hi 8704 | lo 8704], pitch-68 rows
__device__ uint32_t g_W2hl[2 * KD * 68];   // [hi 2176 | lo 2176]

// ---------- helpers ----------
static __device__ __forceinline__ ull pk2(float lo, float hi) {
    ull r; asm("mov.b64 %0,{%1,%2};" : "=l"(r) : "f"(lo), "f"(hi)); return r;
}
static __device__ __forceinline__ float2 upk2(ull v) {
    float2 f; asm("mov.b64 {%0,%1},%2;" : "=f"(f.x), "=f"(f.y) : "l"(v)); return f;
}
static __device__ __forceinline__ ull ffma2_(ull a, ull b, ull c) {
    ull d; asm("fma.rn.f32x2 %0,%1,%2,%3;" : "=l"(d) : "l"(a), "l"(b), "l"(c)); return d;
}
// split (a,b) into bf16 hi pair + bf16 lo pair (residual)
static __device__ __forceinline__ void split_pack(float a, float b, uint32_t& h, uint32_t& l) {
    __nv_bfloat162 th = __floats2bfloat162_rn(a, b);
    uint32_t hp = *(uint32_t*)&th;
    float ha = __uint_as_float(hp << 16);
    float hb = __uint_as_float(hp & 0xFFFF0000u);
    __nv_bfloat162 tl = __floats2bfloat162_rn(a - ha, b - hb);
    h = hp;
    l = *(uint32_t*)&tl;
}
static __device__ __forceinline__ void mma_bf16(float* d, const uint32_t* a,
                                                uint32_t b0, uint32_t b1) {
    asm volatile(
        "mma.sync.aligned.m16n8k16.row.col.f32.bf16.bf16.f32 "
        "{%0,%1,%2,%3}, {%4,%5,%6,%7}, {%8,%9}, {%0,%1,%2,%3};"
        : "+f"(d[0]), "+f"(d[1]), "+f"(d[2]), "+f"(d[3])
        : "r"(a[0]), "r"(a[1]), "r"(a[2]), "r"(a[3]), "r"(b0), "r"(b1));
}

__global__ void hp_zero_kernel(float4* __restrict__ o, int n4) {
    int i = blockIdx.x * blockDim.x + threadIdx.x;
    float4 z = make_float4(0.f, 0.f, 0.f, 0.f);
    for (; i < n4; i += gridDim.x * blockDim.x) o[i] = z;
}

// pre-split weights into bf16 hi/lo pair tiles (pitch-68 uint32 rows, B-operand layout)
__global__ void hp_prep_kernel(const float* __restrict__ W1, const float* __restrict__ W2) {
    int idx = blockIdx.x * blockDim.x + threadIdx.x;
    if (idx < CC * 68) {
        int c = idx / 68, p = idx % 68;
        uint32_t h = 0, l = 0;
        if (p < 64) {
            float v0 = W1[(2 * p) * CC + c];
            float v1 = W1[(2 * p + 1) * CC + c];
            split_pack(v0, v1, h, l);
        }
        g_W1hl[idx] = h;
        g_W1hl[CC * 68 + idx] = l;
    } else if (idx < CC * 68 + KD * 68) {
        int i = idx - CC * 68;
        int k = i / 68, p = i % 68;
        uint32_t h = 0, l = 0;
        if (p < 64) {
            float v0 = W2[(2 * p) * KD + k];
            float v1 = W2[(2 * p + 1) * KD + k];
            split_pack(v0, v1, h, l);
        }
        g_W2hl[i] = h;
        g_W2hl[KD * 68 + i] = l;
    }
}

__global__ __launch_bounds__(THREADS, 1)
void hp_main_kernel(const float* __restrict__ x, const int* __restrict__ batch,
                    const float* __restrict__ b1, const float* __restrict__ b2,
                    float* __restrict__ out, float* __restrict__ s_out, int N)
{
    extern __shared__ __align__(16) float smem[];
    float4*   xn4 = (float4*)(smem + XF_F);        // pitch 33
    uint32_t* XH  = (uint32_t*)(smem + XH_F);      // pitch 68 (also H hi)
    uint32_t* XL  = (uint32_t*)(smem + XL_F);      // pitch 68 (also H lo)
    uint32_t* W1H = (uint32_t*)(smem + W1H_F);     // pitch 68
    uint32_t* W1L = (uint32_t*)(smem + W1L_F);
    uint32_t* W2H = (uint32_t*)(smem + W2H_F);     // pitch 68
    uint32_t* W2L = (uint32_t*)(smem + W2L_F);
    float*    ss  = smem + SS_F;                   // pitch 36
    float4*   ss4 = (float4*)ss;                   // pitch 9
    float*    b1s = smem + B1_F;
    float*    b2s = smem + B2_F;
    int*      ib  = (int*)(smem + IB_I);

    const int tid  = threadIdx.x;
    const int lane = tid & 31;
    const int wid  = tid >> 5;          // 0..7
    const int qr   = lane >> 2;         // 0..7
    const int qc   = lane & 3;          // 0..3
    const int n0   = blockIdx.x * TN;
    const int nvalid = min(TN, N - n0);

    // ================= staging =================
    if (tid < TN) ib[tid] = (n0 + tid < N) ? batch[n0 + tid] : -1;
    if (tid < CC) b1s[tid] = b1[tid];
    if (tid < KD) b2s[tid] = b2[tid];
    {
        const float4* xg = (const float4*)x;
        #pragma unroll
        for (int it = 0; it < (TN * 32) / THREADS; ++it) {   // 16
            int idx = it * THREADS + tid;
            int n = idx >> 5, g = idx & 31;
            float4 v = make_float4(0.f, 0.f, 0.f, 0.f);
            if (n < nvalid) v = xg[(size_t)(n0 + n) * 32 + g];
            xn4[n * 33 + g] = v;
            uint32_t h0, l0, h1, l1;
            split_pack(v.x, v.y, h0, l0);
            split_pack(v.z, v.w, h1, l1);
            XH[n * 68 + 2 * g]     = h0;
            XH[n * 68 + 2 * g + 1] = h1;
            XL[n * 68 + 2 * g]     = l0;
            XL[n * 68 + 2 * g + 1] = l1;
        }
        // weight tiles: flat copies (identical pitch-68 layout in global)
        const float4* s1 = (const float4*)g_W1hl;
        float4* d1 = (float4*)W1H;                   // W1H then W1L contiguous
        #pragma unroll
        for (int it = 0; it < (2 * CC * 68 / 4) / THREADS; ++it)   // 17
            d1[it * THREADS + tid] = s1[it * THREADS + tid];
        #pragma unroll
        for (int it = 0; it < (2 * KD * 68) / THREADS; ++it)       // 17 (uint32)
            W2H[it * THREADS + tid] = g_W2hl[it * THREADS + tid];
    }
    __syncthreads();

    // ===== GEMM1: H = relu(X @ W1 + b1)  3-pass bf16 mma.m16n8k16 =====
    const int mbase = (wid >> 2) * 64;
    const int cbase = (wid & 3) * 32;
    float acc[4][4][4];
    {
        #pragma unroll
        for (int mt = 0; mt < 4; ++mt)
            #pragma unroll
            for (int nt = 0; nt < 4; ++nt)
                #pragma unroll
                for (int e = 0; e < 4; ++e) acc[mt][nt][e] = 0.f;

        for (int ks = 0; ks < 8; ++ks) {
            const int kb2 = ks * 8;                      // uint32 (k-pair) offset
            uint32_t ah[4][4], al[4][4];
            #pragma unroll
            for (int mt = 0; mt < 4; ++mt) {
                int r0 = mbase + mt * 16 + qr;
                ah[mt][0] = XH[r0 * 68 + kb2 + qc];
                ah[mt][1] = XH[(r0 + 8) * 68 + kb2 + qc];
                ah[mt][2] = XH[r0 * 68 + kb2 + 4 + qc];
                ah[mt][3] = XH[(r0 + 8) * 68 + kb2 + 4 + qc];
                al[mt][0] = XL[r0 * 68 + kb2 + qc];
                al[mt][1] = XL[(r0 + 8) * 68 + kb2 + qc];
                al[mt][2] = XL[r0 * 68 + kb2 + 4 + qc];
                al[mt][3] = XL[(r0 + 8) * 68 + kb2 + 4 + qc];
            }
            #pragma unroll
            for (int nt = 0; nt < 4; ++nt) {
                int cb = cbase + nt * 8 + qr;
                uint32_t bh0 = W1H[cb * 68 + kb2 + qc];
                uint32_t bh1 = W1H[cb * 68 + kb2 + 4 + qc];
                uint32_t bl0 = W1L[cb * 68 + kb2 + qc];
                uint32_t bl1 = W1L[cb * 68 + kb2 + 4 + qc];
                #pragma unroll
                for (int mt = 0; mt < 4; ++mt) {
                    mma_bf16(acc[mt][nt], ah[mt], bh0, bh1);
                    mma_bf16(acc[mt][nt], al[mt], bh0, bh1);
                    mma_bf16(acc[mt][nt], ah[mt], bl0, bl1);
                }
            }
        }
    }
    __syncthreads();   // all reads of X/W1 tiles done before overlays

    // ---- epilogue 1: relu + bias, write H hi/lo pairs (overlay XH/XL) ----
    {
        #pragma unroll
        for (int mt = 0; mt < 4; ++mt) {
            int r0 = mbase + mt * 16 + qr;
            #pragma unroll
            for (int nt = 0; nt < 4; ++nt) {
                int cb = cbase + nt * 8 + 2 * qc;
                int pidx = (cbase >> 1) + nt * 4 + qc;   // pair index = cb/2
                float v0 = fmaxf(acc[mt][nt][0] + b1s[cb], 0.f);
                float v1 = fmaxf(acc[mt][nt][1] + b1s[cb + 1], 0.f);
                float v2 = fmaxf(acc[mt][nt][2] + b1s[cb], 0.f);
                float v3 = fmaxf(acc[mt][nt][3] + b1s[cb + 1], 0.f);
                uint32_t h, l;
                split_pack(v0, v1, h, l);
                XH[r0 * 68 + pidx] = h;
                XL[r0 * 68 + pidx] = l;
                split_pack(v2, v3, h, l);
                XH[(r0 + 8) * 68 + pidx] = h;
                XL[(r0 + 8) * 68 + pidx] = l;
            }
        }
    }
    __syncthreads();

    // ===== GEMM2: logits = H @ W2 + b2 (warp = m16 tile, 4 n-tiles) =====
    {
        const int r0 = wid * 16 + qr;
        float a2[4][4];
        #pragma unroll
        for (int nt = 0; nt < 4; ++nt)
            #pragma unroll
            for (int e = 0; e < 4; ++e) a2[nt][e] = 0.f;

        for (int js = 0; js < 8; ++js) {
            const int jb2 = js * 8;
            uint32_t ah[4], al[4];
            ah[0] = XH[r0 * 68 + jb2 + qc];
            ah[1] = XH[(r0 + 8) * 68 + jb2 + qc];
            ah[2] = XH[r0 * 68 + jb2 + 4 + qc];
            ah[3] = XH[(r0 + 8) * 68 + jb2 + 4 + qc];
            al[0] = XL[r0 * 68 + jb2 + qc];
            al[1] = XL[(r0 + 8) * 68 + jb2 + qc];
            al[2] = XL[r0 * 68 + jb2 + 4 + qc];
            al[3] = XL[(r0 + 8) * 68 + jb2 + 4 + qc];
            #pragma unroll
            for (int nt = 0; nt < 4; ++nt) {
                int kb = nt * 8 + qr;
                uint32_t bh0 = W2H[kb * 68 + jb2 + qc];
                uint32_t bh1 = W2H[kb * 68 + jb2 + 4 + qc];
                uint32_t bl0 = W2L[kb * 68 + jb2 + qc];
                uint32_t bl1 = W2L[kb * 68 + jb2 + 4 + qc];
                mma_bf16(a2[nt], ah, bh0, bh1);
                mma_bf16(a2[nt], al, bh0, bh1);
                mma_bf16(a2[nt], ah, bl0, bl1);
            }
        }
        #pragma unroll
        for (int nt = 0; nt < 4; ++nt) {
            int kb = nt * 8 + 2 * qc;
            *(float2*)&ss[r0 * 36 + kb] =
                make_float2(a2[nt][0] + b2s[kb], a2[nt][1] + b2s[kb + 1]);
            *(float2*)&ss[(r0 + 8) * 36 + kb] =
                make_float2(a2[nt][2] + b2s[kb], a2[nt][3] + b2s[kb + 1]);
        }
    }
    __syncthreads();

    // ===== softmax per node (8 warps x 16 nodes, lane = k) =====
    {
        #pragma unroll
        for (int i = 0; i < 16; ++i) {
            int n = wid * 16 + i;
            float v = ss[n * 36 + lane];
            float m = v;
            #pragma unroll
            for (int o = 16; o > 0; o >>= 1) m = fmaxf(m, __shfl_xor_sync(0xffffffffu, m, o));
            float e = __expf(v - m);
            float sum = e;
            #pragma unroll
            for (int o = 16; o > 0; o >>= 1) sum += __shfl_xor_sync(0xffffffffu, sum, o);
            float sv = e / sum;
            ss[n * 36 + lane] = sv;
            if (n < nvalid) s_out[(size_t)(n0 + n) * KD + lane] = sv;
        }
    }
    __syncthreads();

    // ===== stage 4: out[b][k][c] += sum_n s[n][k] * x[n][c]  (scalar f32x2) =====
    {
        const int cl = lane & 7;
        const int kq = lane >> 3;
        const int kh = (wid >> 2) * 16;
        const int cq = (wid & 3) * 32;
        const int c0 = cq + cl * 4;
        const int k0 = kh + kq * 4;

        int bmin = ib[0];
        int bmax = ib[nvalid - 1];
        for (int b = bmin; b <= bmax; ++b) {
            ull acc4[4][2];
            #pragma unroll
            for (int kk = 0; kk < 4; ++kk) { acc4[kk][0] = 0ull; acc4[kk][1] = 0ull; }
            for (int n = 0; n < TN; ++n) {
                if (ib[n] != b) continue;        // uniform across block
                float4 sA = ss4[n * 9 + (k0 >> 2)];
                float4 xv = xn4[n * 33 + (c0 >> 2)];
                ull xp0 = pk2(xv.x, xv.y);
                ull xp1 = pk2(xv.z, xv.w);
                float sk[4] = {sA.x, sA.y, sA.z, sA.w};
                #pragma unroll
                for (int kk = 0; kk < 4; ++kk) {
                    ull sp = pk2(sk[kk], sk[kk]);
                    acc4[kk][0] = ffma2_(sp, xp0, acc4[kk][0]);
                    acc4[kk][1] = ffma2_(sp, xp1, acc4[kk][1]);
                }
            }
            float* ob = out + (size_t)b * (KD * CC);
            #pragma unroll
            for (int kk = 0; kk < 4; ++kk) {
                float2 f0 = upk2(acc4[kk][0]);
                float2 f1 = upk2(acc4[kk][1]);
                float* p = &ob[(k0 + kk) * CC + c0];
                atomicAdd(p + 0, f0.x);
                atomicAdd(p + 1, f0.y);
                atomicAdd(p + 2, f1.x);
                atomicAdd(p + 3, f1.y);
            }
        }
    }
}

extern "C" void kernel_launch(void* const* d_in, const int* in_sizes, int n_in,
                              void* d_out, int out_size)
{
    const float* x     = (const float*)d_in[0];
    const int*   batch = (const int*)d_in[1];
    const float* W1    = (const float*)d_in[2];
    const float* b1    = (const float*)d_in[3];
    const float* W2    = (const float*)d_in[4];
    const float* b2    = (const float*)d_in[5];

    const int N = in_sizes[1];
    float* out = (float*)d_out;
    size_t out_elems = (size_t)out_size - (size_t)N * KD;   // B*K*C
    float* s_out = out + out_elems;

    {   // zero pooled output (harness poisons it)
        int n4 = (int)(out_elems / 4);
        int blocks = (n4 + 255) / 256;
        if (blocks > 512) blocks = 512;
        hp_zero_kernel<<<blocks, 256>>>((float4*)out, n4);
    }
    hp_prep_kernel<<<(CC * 68 + KD * 68 + 255) / 256, 256>>>(W1, W2);

    cudaFuncSetAttribute(hp_main_kernel,
                         cudaFuncAttributeMaxDynamicSharedMemorySize, SMEM_BYTES);
    int nb = (N + TN - 1) / TN;
    hp_main_kernel<<<nb, THREADS, SMEM_BYTES>>>(x, batch, b1, b2, out, s_out, N);
}